// round 3
// baseline (speedup 1.0000x reference)
#include <cuda_runtime.h>

// QJLCompressor: out[h,n,t] = sum_d q[h,n,d]*k_quant[h,t,d]
//                           + (1/R) * sum_r (q[h,n,:]@G[:,r]) * sign((k_orig-k_quant)[h,t,:]@G[:,r])
// Collapsed into one batched GEMM with augmented K-dim = D + R = 192:
//   Q'[h,n,:] = [ q[h,n,:] , (q[h,n,:]@G)/R ]
//   K'[h,t,:] = [ k_quant[h,t,:] , sign((k_orig-k_quant)[h,t,:]@G) ]
//   out[h] = Q'[h] @ K'[h]^T

#define HH 32
#define NN 2048
#define TT 2048
#define DD 128
#define RR 64
#define KD 192   // DD + RR

// Scratch (allocation-free rule: __device__ globals). ~50 MB each.
__device__ __align__(16) float g_Qaug[(size_t)HH * NN * KD];
__device__ __align__(16) float g_Kaug[(size_t)HH * TT * KD];

// ---------------------------------------------------------------------------
// Build Q' : copy q row, append (q @ G) / R
// One warp per row; G cached in smem (128x64 fp32 = 32 KB).
// ---------------------------------------------------------------------------
__global__ __launch_bounds__(256) void build_qaug(const float* __restrict__ q,
                                                  const float* __restrict__ G) {
    __shared__ float Gs[DD * RR];
    __shared__ float es[8][DD];

    const int tid = threadIdx.x;
    // cooperative load of G (8192 floats = 2048 float4)
    const float4* G4 = (const float4*)G;
    float4* Gs4 = (float4*)Gs;
    #pragma unroll
    for (int i = tid; i < DD * RR / 4; i += 256) Gs4[i] = G4[i];
    __syncthreads();

    const int warp = tid >> 5;
    const int lane = tid & 31;
    const size_t row = (size_t)blockIdx.x * 8 + warp;  // row in [0, HH*NN)

    const float4* qr = (const float4*)(q + row * DD);
    float4* orow = (float4*)(g_Qaug + row * KD);
    float4 v = qr[lane];            // 32 lanes x 4 floats = 128
    orow[lane] = v;                 // copy q into first 128 cols
    ((float4*)es[warp])[lane] = v;  // stage row for projection
    __syncwarp();

    float a0 = 0.f, a1 = 0.f;
    #pragma unroll
    for (int d = 0; d < DD; ++d) {
        float e = es[warp][d];
        a0 += e * Gs[d * RR + lane];
        a1 += e * Gs[d * RR + lane + 32];
    }
    const float scale = 1.0f / (float)RR;  // (1/sqrt(R)) * (1/sqrt(R))
    g_Qaug[row * KD + DD + lane]      = a0 * scale;
    g_Qaug[row * KD + DD + 32 + lane] = a1 * scale;
}

// ---------------------------------------------------------------------------
// Build K' : copy k_quant row, append sign((k_orig - k_quant) @ G)
// ---------------------------------------------------------------------------
__global__ __launch_bounds__(256) void build_kaug(const float* __restrict__ k_orig,
                                                  const float* __restrict__ k_quant,
                                                  const float* __restrict__ G) {
    __shared__ float Gs[DD * RR];
    __shared__ float es[8][DD];

    const int tid = threadIdx.x;
    const float4* G4 = (const float4*)G;
    float4* Gs4 = (float4*)Gs;
    #pragma unroll
    for (int i = tid; i < DD * RR / 4; i += 256) Gs4[i] = G4[i];
    __syncthreads();

    const int warp = tid >> 5;
    const int lane = tid & 31;
    const size_t row = (size_t)blockIdx.x * 8 + warp;  // row in [0, HH*TT)

    const float4* kq4 = (const float4*)(k_quant + row * DD);
    const float4* ko4 = (const float4*)(k_orig + row * DD);
    float4 vq = kq4[lane];
    float4 vo = ko4[lane];
    float4* orow = (float4*)(g_Kaug + row * KD);
    orow[lane] = vq;  // copy k_quant into first 128 cols
    float4 e4;
    e4.x = vo.x - vq.x; e4.y = vo.y - vq.y; e4.z = vo.z - vq.z; e4.w = vo.w - vq.w;
    ((float4*)es[warp])[lane] = e4;
    __syncwarp();

    float a0 = 0.f, a1 = 0.f;
    #pragma unroll
    for (int d = 0; d < DD; ++d) {
        float e = es[warp][d];
        a0 += e * Gs[d * RR + lane];
        a1 += e * Gs[d * RR + lane + 32];
    }
    float s0 = (a0 > 0.f) ? 1.f : ((a0 < 0.f) ? -1.f : 0.f);
    float s1 = (a1 > 0.f) ? 1.f : ((a1 < 0.f) ? -1.f : 0.f);
    g_Kaug[row * KD + DD + lane]      = s0;
    g_Kaug[row * KD + DD + 32 + lane] = s1;
}

// ---------------------------------------------------------------------------
// Batched SGEMM: C[h] = Q'[h] (N x 192) @ K'[h]^T (192 x T)
// 128x128 tile per CTA, BK=16, 256 threads, 8x8 accum per thread
// (as 2x2 blocks of 4x4 at offsets 0/+64 for conflict-free smem reads).
// ---------------------------------------------------------------------------
__global__ __launch_bounds__(256, 2)
void gemm_aug(float* __restrict__ C) {
    __shared__ float As[16][128];
    __shared__ float Bs[16][128];

    const float* __restrict__ A = g_Qaug;
    const float* __restrict__ B = g_Kaug;

    const int h = blockIdx.z;
    const float* Ab = A + ((size_t)h * NN + (size_t)blockIdx.y * 128) * KD;
    const float* Bb = B + ((size_t)h * TT + (size_t)blockIdx.x * 128) * KD;
    float* Cb = C + (size_t)h * NN * TT;

    const int tid  = threadIdx.x;
    const int lrow = tid >> 2;         // 0..63
    const int lcol = (tid & 3) << 2;   // 0,4,8,12
    const int tx   = tid & 15;         // 0..15
    const int ty   = tid >> 4;         // 0..15

    float acc[8][8];
    #pragma unroll
    for (int i = 0; i < 8; ++i)
        #pragma unroll
        for (int j = 0; j < 8; ++j) acc[i][j] = 0.f;

    for (int kt = 0; kt < KD; kt += 16) {
        float4 a0 = *(const float4*)(Ab + (size_t)lrow * KD + kt + lcol);
        float4 a1 = *(const float4*)(Ab + (size_t)(lrow + 64) * KD + kt + lcol);
        float4 b0 = *(const float4*)(Bb + (size_t)lrow * KD + kt + lcol);
        float4 b1 = *(const float4*)(Bb + (size_t)(lrow + 64) * KD + kt + lcol);

        __syncthreads();
        As[lcol + 0][lrow] = a0.x; As[lcol + 1][lrow] = a0.y;
        As[lcol + 2][lrow] = a0.z; As[lcol + 3][lrow] = a0.w;
        As[lcol + 0][lrow + 64] = a1.x; As[lcol + 1][lrow + 64] = a1.y;
        As[lcol + 2][lrow + 64] = a1.z; As[lcol + 3][lrow + 64] = a1.w;
        Bs[lcol + 0][lrow] = b0.x; Bs[lcol + 1][lrow] = b0.y;
        Bs[lcol + 2][lrow] = b0.z; Bs[lcol + 3][lrow] = b0.w;
        Bs[lcol + 0][lrow + 64] = b1.x; Bs[lcol + 1][lrow + 64] = b1.y;
        Bs[lcol + 2][lrow + 64] = b1.z; Bs[lcol + 3][lrow + 64] = b1.w;
        __syncthreads();

        #pragma unroll
        for (int k = 0; k < 16; ++k) {
            float ar[8], br[8];
            *(float4*)&ar[0] = *(const float4*)&As[k][ty * 4];
            *(float4*)&ar[4] = *(const float4*)&As[k][ty * 4 + 64];
            *(float4*)&br[0] = *(const float4*)&Bs[k][tx * 4];
            *(float4*)&br[4] = *(const float4*)&Bs[k][tx * 4 + 64];
            #pragma unroll
            for (int i = 0; i < 8; ++i)
                #pragma unroll
                for (int j = 0; j < 8; ++j)
                    acc[i][j] += ar[i] * br[j];
        }
    }

    const int rb = blockIdx.y * 128;
    const int cb = blockIdx.x * 128;
    #pragma unroll
    for (int i = 0; i < 8; ++i) {
        int r = rb + ((i < 4) ? (ty * 4 + i) : (64 + ty * 4 + i - 4));
        float4 v0, v1;
        v0.x = acc[i][0]; v0.y = acc[i][1]; v0.z = acc[i][2]; v0.w = acc[i][3];
        v1.x = acc[i][4]; v1.y = acc[i][5]; v1.z = acc[i][6]; v1.w = acc[i][7];
        *(float4*)(Cb + (size_t)r * TT + cb + tx * 4)      = v0;
        *(float4*)(Cb + (size_t)r * TT + cb + 64 + tx * 4) = v1;
    }
}

extern "C" void kernel_launch(void* const* d_in, const int* in_sizes, int n_in,
                              void* d_out, int out_size) {
    const float* q       = (const float*)d_in[0];
    const float* k_orig  = (const float*)d_in[1];
    const float* k_quant = (const float*)d_in[2];
    const float* G       = (const float*)d_in[3];
    float* out = (float*)d_out;

    build_qaug<<<(HH * NN) / 8, 256>>>(q, G);
    build_kaug<<<(HH * TT) / 8, 256>>>(k_orig, k_quant, G);

    dim3 grid(TT / 128, NN / 128, HH);
    gemm_aug<<<grid, 256>>>(out);
}

// round 5
// speedup vs baseline: 1.4097x; 1.4097x over previous
#include <cuda_runtime.h>
#include <cuda_bf16.h>
#include <cstdint>

// out[h,n,t] = q·k_quant^T + (qG/R)·sign((k_orig-k_quant)G)^T
// Augmented GEMM (K-dim 192) on warp-level bf16 HMMA (mma.sync, base sm_103 ISA),
// split-bf16 3-pass: C = Qh@Kh^T + Qh@Kl^T + Ql@Kh^T (ll dropped, ~4e-6 rel).

#define HH 32
#define NN 2048
#define TT 2048
#define DD 128
#define RR 64
#define KD 192

__device__ __align__(16) __nv_bfloat16 g_Qh[(size_t)HH * NN * KD];
__device__ __align__(16) __nv_bfloat16 g_Ql[(size_t)HH * NN * KD];
__device__ __align__(16) __nv_bfloat16 g_Kh[(size_t)HH * TT * KD];
__device__ __align__(16) __nv_bfloat16 g_Kl[(size_t)HH * TT * KD];

static __device__ __forceinline__ uint32_t smem_u32(const void* p) {
    uint32_t a;
    asm("{ .reg .u64 t; cvta.to.shared.u64 t, %1; cvt.u32.u64 %0, t; }"
        : "=r"(a) : "l"(p));
    return a;
}

static __device__ __forceinline__ void cp16(uint32_t d, const void* s) {
    asm volatile("cp.async.cg.shared.global [%0], [%1], 16;" :: "r"(d), "l"(s) : "memory");
}

static __device__ __forceinline__ void ldsm4(uint32_t& r0, uint32_t& r1, uint32_t& r2,
                                             uint32_t& r3, uint32_t a) {
    asm volatile("ldmatrix.sync.aligned.m8n8.x4.shared.b16 {%0,%1,%2,%3}, [%4];"
                 : "=r"(r0), "=r"(r1), "=r"(r2), "=r"(r3) : "r"(a));
}

static __device__ __forceinline__ void mma16816(float* c, const uint32_t* a, const uint32_t* b) {
    asm volatile(
        "mma.sync.aligned.m16n8k16.row.col.f32.bf16.bf16.f32 "
        "{%0,%1,%2,%3}, {%4,%5,%6,%7}, {%8,%9}, {%0,%1,%2,%3};"
        : "+f"(c[0]), "+f"(c[1]), "+f"(c[2]), "+f"(c[3])
        : "r"(a[0]), "r"(a[1]), "r"(a[2]), "r"(a[3]), "r"(b[0]), "r"(b[1]));
}

static __device__ __forceinline__ uint32_t pack_bf2(__nv_bfloat16 a, __nv_bfloat16 b) {
    __nv_bfloat162 t = __halves2bfloat162(a, b);
    return *reinterpret_cast<uint32_t*>(&t);
}

// ---------------------------------------------------------------------------
// Prep Q: split q into bf16 hi/lo, append proj = (q@G)/R split hi/lo.
// ---------------------------------------------------------------------------
__global__ __launch_bounds__(256) void prep_q(const float* __restrict__ q,
                                              const float* __restrict__ G) {
    __shared__ float Gs[DD * RR];
    __shared__ float Es[32][DD];
    const int tid = threadIdx.x;

    const float4* G4 = (const float4*)G;
    float4* Gs4 = (float4*)Gs;
    #pragma unroll
    for (int i = tid; i < DD * RR / 4; i += 256) Gs4[i] = G4[i];

    const size_t row0 = (size_t)blockIdx.x * 32;
    #pragma unroll
    for (int i = tid; i < 32 * 32; i += 256) {
        int r = i >> 5, c = i & 31;
        float4 v = *(const float4*)(q + (row0 + r) * DD + c * 4);
        *(float4*)(&Es[r][c * 4]) = v;
        float x[4] = {v.x, v.y, v.z, v.w};
        __nv_bfloat16 h[4], l[4];
        #pragma unroll
        for (int j = 0; j < 4; ++j) {
            h[j] = __float2bfloat16_rn(x[j]);
            l[j] = __float2bfloat16_rn(x[j] - __bfloat162float(h[j]));
        }
        size_t o = (row0 + r) * KD + c * 4;
        *(uint2*)(&g_Qh[o]) = make_uint2(pack_bf2(h[0], h[1]), pack_bf2(h[2], h[3]));
        *(uint2*)(&g_Ql[o]) = make_uint2(pack_bf2(l[0], l[1]), pack_bf2(l[2], l[3]));
    }
    __syncthreads();

    const int w = tid >> 5, lane = tid & 31;
    const int r0 = w * 4;
    float a0[4] = {0.f, 0.f, 0.f, 0.f}, a1[4] = {0.f, 0.f, 0.f, 0.f};
    #pragma unroll 4
    for (int d = 0; d < DD; ++d) {
        float gA = Gs[d * RR + lane];
        float gB = Gs[d * RR + 32 + lane];
        #pragma unroll
        for (int j = 0; j < 4; ++j) {
            float e = Es[r0 + j][d];
            a0[j] += e * gA;
            a1[j] += e * gB;
        }
    }
    const float sc = 1.0f / (float)RR;
    #pragma unroll
    for (int j = 0; j < 4; ++j) {
        float p0 = a0[j] * sc, p1 = a1[j] * sc;
        size_t o = (row0 + r0 + j) * KD + DD;
        __nv_bfloat16 h0 = __float2bfloat16_rn(p0);
        __nv_bfloat16 h1 = __float2bfloat16_rn(p1);
        g_Qh[o + lane]      = h0;
        g_Qh[o + 32 + lane] = h1;
        g_Ql[o + lane]      = __float2bfloat16_rn(p0 - __bfloat162float(h0));
        g_Ql[o + 32 + lane] = __float2bfloat16_rn(p1 - __bfloat162float(h1));
    }
}

// ---------------------------------------------------------------------------
// Prep K: split k_quant hi/lo, append sign((k_orig-k_quant)@G) (exact in bf16).
// ---------------------------------------------------------------------------
__global__ __launch_bounds__(256) void prep_k(const float* __restrict__ k_orig,
                                              const float* __restrict__ k_quant,
                                              const float* __restrict__ G) {
    __shared__ float Gs[DD * RR];
    __shared__ float Es[32][DD];
    const int tid = threadIdx.x;

    const float4* G4 = (const float4*)G;
    float4* Gs4 = (float4*)Gs;
    #pragma unroll
    for (int i = tid; i < DD * RR / 4; i += 256) Gs4[i] = G4[i];

    const size_t row0 = (size_t)blockIdx.x * 32;
    #pragma unroll
    for (int i = tid; i < 32 * 32; i += 256) {
        int r = i >> 5, c = i & 31;
        float4 vq = *(const float4*)(k_quant + (row0 + r) * DD + c * 4);
        float4 vo = *(const float4*)(k_orig + (row0 + r) * DD + c * 4);
        float4 e4;
        e4.x = vo.x - vq.x; e4.y = vo.y - vq.y;
        e4.z = vo.z - vq.z; e4.w = vo.w - vq.w;
        *(float4*)(&Es[r][c * 4]) = e4;
        float x[4] = {vq.x, vq.y, vq.z, vq.w};
        __nv_bfloat16 h[4], l[4];
        #pragma unroll
        for (int j = 0; j < 4; ++j) {
            h[j] = __float2bfloat16_rn(x[j]);
            l[j] = __float2bfloat16_rn(x[j] - __bfloat162float(h[j]));
        }
        size_t o = (row0 + r) * KD + c * 4;
        *(uint2*)(&g_Kh[o]) = make_uint2(pack_bf2(h[0], h[1]), pack_bf2(h[2], h[3]));
        *(uint2*)(&g_Kl[o]) = make_uint2(pack_bf2(l[0], l[1]), pack_bf2(l[2], l[3]));
    }
    __syncthreads();

    const int w = tid >> 5, lane = tid & 31;
    const int r0 = w * 4;
    float a0[4] = {0.f, 0.f, 0.f, 0.f}, a1[4] = {0.f, 0.f, 0.f, 0.f};
    #pragma unroll 4
    for (int d = 0; d < DD; ++d) {
        float gA = Gs[d * RR + lane];
        float gB = Gs[d * RR + 32 + lane];
        #pragma unroll
        for (int j = 0; j < 4; ++j) {
            float e = Es[r0 + j][d];
            a0[j] += e * gA;
            a1[j] += e * gB;
        }
    }
    const __nv_bfloat16 z = __float2bfloat16_rn(0.f);
    #pragma unroll
    for (int j = 0; j < 4; ++j) {
        float s0 = (a0[j] > 0.f) ? 1.f : ((a0[j] < 0.f) ? -1.f : 0.f);
        float s1 = (a1[j] > 0.f) ? 1.f : ((a1[j] < 0.f) ? -1.f : 0.f);
        size_t o = (row0 + r0 + j) * KD + DD;
        g_Kh[o + lane]      = __float2bfloat16_rn(s0);
        g_Kh[o + 32 + lane] = __float2bfloat16_rn(s1);
        g_Kl[o + lane]      = z;
        g_Kl[o + 32 + lane] = z;
    }
}

// ---------------------------------------------------------------------------
// HMMA GEMM: CTA tile 128(M) x 256(N), 256 threads, warp tile 64x64.
// K: 36 steps of 16 bf16 (3 passes x 192). 4-stage cp.async pipeline.
// smem rows padded to 48B -> conflict-free ldmatrix (phase 3r mod 8).
// ---------------------------------------------------------------------------
#define A_BYTES 6144              // 128 rows * 48B
#define B_BYTES 12288             // 256 rows * 48B
#define STAGE   18432
#define NSTAGES 4
#define SMEM_TOTAL (STAGE * NSTAGES)   // 73728
#define KSTEPS  36

__global__ __launch_bounds__(256) void gemm_hmma(float* __restrict__ C) {
    extern __shared__ char sm[];
    const uint32_t smb = smem_u32(sm);
    const int tid = threadIdx.x, lane = tid & 31, wid = tid >> 5;
    const int wm = wid & 1;        // 0..1  -> 64-row m slot
    const int wn = wid >> 1;       // 0..3  -> 64-col n slot

    const size_t arow0 = (size_t)blockIdx.z * NN + (size_t)blockIdx.y * 128;
    const size_t brow0 = (size_t)blockIdx.z * TT + (size_t)blockIdx.x * 256;

    auto loadStage = [&](int kk) {
        const int p = (kk >= 24) ? 2 : ((kk >= 12) ? 1 : 0);
        const int c0 = (kk - p * 12) * 16;
        const __nv_bfloat16* Asrc = (p == 2) ? g_Ql : g_Qh;
        const __nv_bfloat16* Bsrc = (p == 1) ? g_Kl : g_Kh;
        const uint32_t sA = smb + (kk & 3) * STAGE;
        const uint32_t sB = sA + A_BYTES;
        {
            int r = tid >> 1, c = tid & 1;
            const char* src = (const char*)(Asrc + (arow0 + r) * KD + c0) + c * 16;
            cp16(sA + r * 48 + c * 16, src);
        }
        #pragma unroll
        for (int i = 0; i < 2; ++i) {
            int id = tid + (i << 8);
            int r = id >> 1, c = id & 1;
            const char* src = (const char*)(Bsrc + (brow0 + r) * KD + c0) + c * 16;
            cp16(sB + r * 48 + c * 16, src);
        }
        asm volatile("cp.async.commit_group;" ::: "memory");
    };

    float acc[4][8][4];
    #pragma unroll
    for (int i = 0; i < 4; ++i)
        #pragma unroll
        for (int j = 0; j < 8; ++j)
            #pragma unroll
            for (int v = 0; v < 4; ++v) acc[i][j][v] = 0.f;

    loadStage(0);
    loadStage(1);
    loadStage(2);

    // ldmatrix lane address bases (stage 0): r = lane&15, khalf = lane>>4
    const uint32_t aB = smb + (uint32_t)(wm * 64 + (lane & 15)) * 48 + (lane >> 4) * 16;
    const uint32_t bB = smb + A_BYTES + (uint32_t)(wn * 64 + (lane & 15)) * 48 + (lane >> 4) * 16;

    #pragma unroll 1
    for (int kk = 0; kk < KSTEPS; ++kk) {
        asm volatile("cp.async.wait_group 2;" ::: "memory");
        __syncthreads();
        if (kk + 3 < KSTEPS) loadStage(kk + 3);
        else asm volatile("cp.async.commit_group;" ::: "memory");  // keep group count uniform

        const uint32_t so = (kk & 3) * STAGE;
        uint32_t a[4][4];
        #pragma unroll
        for (int mt = 0; mt < 4; ++mt)
            ldsm4(a[mt][0], a[mt][1], a[mt][2], a[mt][3], aB + so + mt * (16 * 48));
        uint32_t b[8][2];
        #pragma unroll
        for (int nb = 0; nb < 4; ++nb) {
            uint32_t r0, r1, r2, r3;
            ldsm4(r0, r1, r2, r3, bB + so + nb * (16 * 48));
            b[2 * nb][0] = r0; b[2 * nb][1] = r2;
            b[2 * nb + 1][0] = r1; b[2 * nb + 1][1] = r3;
        }
        #pragma unroll
        for (int mt = 0; mt < 4; ++mt)
            #pragma unroll
            for (int nt = 0; nt < 8; ++nt)
                mma16816(acc[mt][nt], a[mt], b[nt]);
    }

    // Epilogue: accum regs -> global
    float* Cb = C + ((size_t)blockIdx.z * NN + (size_t)blockIdx.y * 128 + wm * 64) * TT
                  + (size_t)blockIdx.x * 256 + wn * 64;
    const int r = lane >> 2, cc = (lane & 3) * 2;
    #pragma unroll
    for (int mt = 0; mt < 4; ++mt) {
        #pragma unroll
        for (int nt = 0; nt < 8; ++nt) {
            float2 v0 = make_float2(acc[mt][nt][0], acc[mt][nt][1]);
            float2 v1 = make_float2(acc[mt][nt][2], acc[mt][nt][3]);
            *(float2*)(Cb + (size_t)(mt * 16 + r) * TT + nt * 8 + cc) = v0;
            *(float2*)(Cb + (size_t)(mt * 16 + r + 8) * TT + nt * 8 + cc) = v1;
        }
    }
}

// ---------------------------------------------------------------------------
extern "C" void kernel_launch(void* const* d_in, const int* in_sizes, int n_in,
                              void* d_out, int out_size) {
    const float* q       = (const float*)d_in[0];
    const float* k_orig  = (const float*)d_in[1];
    const float* k_quant = (const float*)d_in[2];
    const float* G       = (const float*)d_in[3];
    float* out = (float*)d_out;

    cudaFuncSetAttribute(gemm_hmma, cudaFuncAttributeMaxDynamicSharedMemorySize, SMEM_TOTAL);

    prep_q<<<HH * NN / 32, 256>>>(q, G);
    prep_k<<<HH * TT / 32, 256>>>(k_orig, k_quant, G);

    dim3 grid(TT / 256, NN / 128, HH);
    gemm_hmma<<<grid, 256, SMEM_TOTAL>>>(out);
}

// round 6
// speedup vs baseline: 3.1502x; 2.2346x over previous
#include <cuda_runtime.h>
#include <cuda_fp16.h>
#include <cstdint>

// out[h,n,t] = q·k_quant^T + (qG/R)·sign((k_orig-k_quant)G)^T
// Single-pass fp16 augmented GEMM, K = 192:
//   Q'[h,n,:] = [ fp16(q) , fp16((q@G)/R) ]
//   K'[h,t,:] = [ fp16(k_quant) , fp16(sign((k_orig-k_quant)@G)) ]   (sign in fp32!)
// fp16 input rounding => ~2.8e-4 global rel err (threshold 1e-3).

#define HH 32
#define NN 2048
#define TT 2048
#define DD 128
#define RR 64
#define KD 192

__device__ __align__(16) __half g_Qa[(size_t)HH * NN * KD];
__device__ __align__(16) __half g_Ka[(size_t)HH * TT * KD];

static __device__ __forceinline__ uint32_t smem_u32(const void* p) {
    uint32_t a;
    asm("{ .reg .u64 t; cvta.to.shared.u64 t, %1; cvt.u32.u64 %0, t; }"
        : "=r"(a) : "l"(p));
    return a;
}

static __device__ __forceinline__ void cp16(uint32_t d, const void* s) {
    asm volatile("cp.async.cg.shared.global [%0], [%1], 16;" :: "r"(d), "l"(s) : "memory");
}

static __device__ __forceinline__ void ldsm4(uint32_t& r0, uint32_t& r1, uint32_t& r2,
                                             uint32_t& r3, uint32_t a) {
    asm volatile("ldmatrix.sync.aligned.m8n8.x4.shared.b16 {%0,%1,%2,%3}, [%4];"
                 : "=r"(r0), "=r"(r1), "=r"(r2), "=r"(r3) : "r"(a));
}

static __device__ __forceinline__ void mma16816(float* c, const uint32_t* a, const uint32_t* b) {
    asm volatile(
        "mma.sync.aligned.m16n8k16.row.col.f32.f16.f16.f32 "
        "{%0,%1,%2,%3}, {%4,%5,%6,%7}, {%8,%9}, {%0,%1,%2,%3};"
        : "+f"(c[0]), "+f"(c[1]), "+f"(c[2]), "+f"(c[3])
        : "r"(a[0]), "r"(a[1]), "r"(a[2]), "r"(a[3]), "r"(b[0]), "r"(b[1]));
}

static __device__ __forceinline__ uint32_t pack_h2(__half a, __half b) {
    __half2 t = __halves2half2(a, b);
    return *reinterpret_cast<uint32_t*>(&t);
}

// ---------------------------------------------------------------------------
// Prep Q: fp16(q) into cols 0..127, fp16((q@G)/R) into cols 128..191.
// Projection computed in fp32 (accuracy irrelevant here but cheap).
// ---------------------------------------------------------------------------
__global__ __launch_bounds__(256) void prep_q(const float* __restrict__ q,
                                              const float* __restrict__ G) {
    __shared__ float Gs[DD * RR];
    __shared__ float Es[32][DD];
    const int tid = threadIdx.x;

    const float4* G4 = (const float4*)G;
    float4* Gs4 = (float4*)Gs;
    #pragma unroll
    for (int i = tid; i < DD * RR / 4; i += 256) Gs4[i] = G4[i];

    const size_t row0 = (size_t)blockIdx.x * 32;
    #pragma unroll
    for (int i = tid; i < 32 * 32; i += 256) {
        int r = i >> 5, c = i & 31;
        float4 v = *(const float4*)(q + (row0 + r) * DD + c * 4);
        *(float4*)(&Es[r][c * 4]) = v;
        size_t o = (row0 + r) * KD + c * 4;
        *(uint2*)(&g_Qa[o]) = make_uint2(
            pack_h2(__float2half_rn(v.x), __float2half_rn(v.y)),
            pack_h2(__float2half_rn(v.z), __float2half_rn(v.w)));
    }
    __syncthreads();

    const int w = tid >> 5, lane = tid & 31;
    const int r0 = w * 4;
    float a0[4] = {0.f, 0.f, 0.f, 0.f}, a1[4] = {0.f, 0.f, 0.f, 0.f};
    #pragma unroll 4
    for (int d = 0; d < DD; ++d) {
        float gA = Gs[d * RR + lane];
        float gB = Gs[d * RR + 32 + lane];
        #pragma unroll
        for (int j = 0; j < 4; ++j) {
            float e = Es[r0 + j][d];
            a0[j] += e * gA;
            a1[j] += e * gB;
        }
    }
    const float sc = 1.0f / (float)RR;
    #pragma unroll
    for (int j = 0; j < 4; ++j) {
        size_t o = (row0 + r0 + j) * KD + DD;
        g_Qa[o + lane]      = __float2half_rn(a0[j] * sc);
        g_Qa[o + 32 + lane] = __float2half_rn(a1[j] * sc);
    }
}

// ---------------------------------------------------------------------------
// Prep K: fp16(k_quant) into cols 0..127, fp16(sign((k_orig-k_quant)@G))
// into cols 128..191. Sign computed in fp32 (precision-critical).
// ---------------------------------------------------------------------------
__global__ __launch_bounds__(256) void prep_k(const float* __restrict__ k_orig,
                                              const float* __restrict__ k_quant,
                                              const float* __restrict__ G) {
    __shared__ float Gs[DD * RR];
    __shared__ float Es[32][DD];
    const int tid = threadIdx.x;

    const float4* G4 = (const float4*)G;
    float4* Gs4 = (float4*)Gs;
    #pragma unroll
    for (int i = tid; i < DD * RR / 4; i += 256) Gs4[i] = G4[i];

    const size_t row0 = (size_t)blockIdx.x * 32;
    #pragma unroll
    for (int i = tid; i < 32 * 32; i += 256) {
        int r = i >> 5, c = i & 31;
        float4 vq = *(const float4*)(k_quant + (row0 + r) * DD + c * 4);
        float4 vo = *(const float4*)(k_orig + (row0 + r) * DD + c * 4);
        float4 e4;
        e4.x = vo.x - vq.x; e4.y = vo.y - vq.y;
        e4.z = vo.z - vq.z; e4.w = vo.w - vq.w;
        *(float4*)(&Es[r][c * 4]) = e4;
        size_t o = (row0 + r) * KD + c * 4;
        *(uint2*)(&g_Ka[o]) = make_uint2(
            pack_h2(__float2half_rn(vq.x), __float2half_rn(vq.y)),
            pack_h2(__float2half_rn(vq.z), __float2half_rn(vq.w)));
    }
    __syncthreads();

    const int w = tid >> 5, lane = tid & 31;
    const int r0 = w * 4;
    float a0[4] = {0.f, 0.f, 0.f, 0.f}, a1[4] = {0.f, 0.f, 0.f, 0.f};
    #pragma unroll 4
    for (int d = 0; d < DD; ++d) {
        float gA = Gs[d * RR + lane];
        float gB = Gs[d * RR + 32 + lane];
        #pragma unroll
        for (int j = 0; j < 4; ++j) {
            float e = Es[r0 + j][d];
            a0[j] += e * gA;
            a1[j] += e * gB;
        }
    }
    #pragma unroll
    for (int j = 0; j < 4; ++j) {
        float s0 = (a0[j] > 0.f) ? 1.f : ((a0[j] < 0.f) ? -1.f : 0.f);
        float s1 = (a1[j] > 0.f) ? 1.f : ((a1[j] < 0.f) ? -1.f : 0.f);
        size_t o = (row0 + r0 + j) * KD + DD;
        g_Ka[o + lane]      = __float2half_rn(s0);
        g_Ka[o + 32 + lane] = __float2half_rn(s1);
    }
}

// ---------------------------------------------------------------------------
// HMMA GEMM: CTA tile 128(M) x 256(N), 256 threads, warp tile 64x64.
// K: 12 steps of 16 fp16. 4-stage cp.async pipeline. 48B-padded smem rows
// (conflict-free ldmatrix: 3r mod 8 distinct).
// ---------------------------------------------------------------------------
#define A_BYTES 6144              // 128 rows * 48B
#define STAGE   18432             // A 6KB + B 12KB
#define SMEM_TOTAL (STAGE * 4)    // 73728
#define KSTEPS  12

__global__ __launch_bounds__(256) void gemm_hmma(float* __restrict__ C) {
    extern __shared__ char sm[];
    const uint32_t smb = smem_u32(sm);
    const int tid = threadIdx.x, lane = tid & 31, wid = tid >> 5;
    const int wm = wid & 1;        // 0..1  -> 64-row m slot
    const int wn = wid >> 1;       // 0..3  -> 64-col n slot

    const size_t arow0 = (size_t)blockIdx.z * NN + (size_t)blockIdx.y * 128;
    const size_t brow0 = (size_t)blockIdx.z * TT + (size_t)blockIdx.x * 256;

    auto loadStage = [&](int kk) {
        const int c0 = kk * 16;
        const uint32_t sA = smb + (kk & 3) * STAGE;
        const uint32_t sB = sA + A_BYTES;
        {
            int r = tid >> 1, c = tid & 1;
            const char* src = (const char*)(g_Qa + (arow0 + r) * KD + c0) + c * 16;
            cp16(sA + r * 48 + c * 16, src);
        }
        #pragma unroll
        for (int i = 0; i < 2; ++i) {
            int id = tid + (i << 8);
            int r = id >> 1, c = id & 1;
            const char* src = (const char*)(g_Ka + (brow0 + r) * KD + c0) + c * 16;
            cp16(sB + r * 48 + c * 16, src);
        }
        asm volatile("cp.async.commit_group;" ::: "memory");
    };

    float acc[4][8][4];
    #pragma unroll
    for (int i = 0; i < 4; ++i)
        #pragma unroll
        for (int j = 0; j < 8; ++j)
            #pragma unroll
            for (int v = 0; v < 4; ++v) acc[i][j][v] = 0.f;

    loadStage(0);
    loadStage(1);
    loadStage(2);

    const uint32_t aB = smb + (uint32_t)(wm * 64 + (lane & 15)) * 48 + (lane >> 4) * 16;
    const uint32_t bB = smb + A_BYTES + (uint32_t)(wn * 64 + (lane & 15)) * 48 + (lane >> 4) * 16;

    #pragma unroll 1
    for (int kk = 0; kk < KSTEPS; ++kk) {
        asm volatile("cp.async.wait_group 2;" ::: "memory");
        __syncthreads();
        if (kk + 3 < KSTEPS) loadStage(kk + 3);
        else asm volatile("cp.async.commit_group;" ::: "memory");

        const uint32_t so = (kk & 3) * STAGE;
        uint32_t a[4][4];
        #pragma unroll
        for (int mt = 0; mt < 4; ++mt)
            ldsm4(a[mt][0], a[mt][1], a[mt][2], a[mt][3], aB + so + mt * (16 * 48));
        uint32_t b[8][2];
        #pragma unroll
        for (int nb = 0; nb < 4; ++nb) {
            uint32_t r0, r1, r2, r3;
            ldsm4(r0, r1, r2, r3, bB + so + nb * (16 * 48));
            b[2 * nb][0] = r0; b[2 * nb][1] = r2;
            b[2 * nb + 1][0] = r1; b[2 * nb + 1][1] = r3;
        }
        #pragma unroll
        for (int mt = 0; mt < 4; ++mt)
            #pragma unroll
            for (int nt = 0; nt < 8; ++nt)
                mma16816(acc[mt][nt], a[mt], b[nt]);
    }

    // Epilogue: streaming stores (C never re-read; keep L2 for A/B reuse)
    float* Cb = C + ((size_t)blockIdx.z * NN + (size_t)blockIdx.y * 128 + wm * 64) * TT
                  + (size_t)blockIdx.x * 256 + wn * 64;
    const int r = lane >> 2, cc = (lane & 3) * 2;
    #pragma unroll
    for (int mt = 0; mt < 4; ++mt) {
        #pragma unroll
        for (int nt = 0; nt < 8; ++nt) {
            float2 v0 = make_float2(acc[mt][nt][0], acc[mt][nt][1]);
            float2 v1 = make_float2(acc[mt][nt][2], acc[mt][nt][3]);
            __stcs((float2*)(Cb + (size_t)(mt * 16 + r) * TT + nt * 8 + cc), v0);
            __stcs((float2*)(Cb + (size_t)(mt * 16 + r + 8) * TT + nt * 8 + cc), v1);
        }
    }
}

// ---------------------------------------------------------------------------
extern "C" void kernel_launch(void* const* d_in, const int* in_sizes, int n_in,
                              void* d_out, int out_size) {
    const float* q       = (const float*)d_in[0];
    const float* k_orig  = (const float*)d_in[1];
    const float* k_quant = (const float*)d_in[2];
    const float* G       = (const float*)d_in[3];
    float* out = (float*)d_out;

    cudaFuncSetAttribute(gemm_hmma, cudaFuncAttributeMaxDynamicSharedMemorySize, SMEM_TOTAL);

    prep_q<<<HH * NN / 32, 256>>>(q, G);
    prep_k<<<HH * TT / 32, 256>>>(k_orig, k_quant, G);

    dim3 grid(TT / 256, NN / 128, HH);
    gemm_hmma<<<grid, 256, SMEM_TOTAL>>>(out);
}

// round 7
// speedup vs baseline: 3.1851x; 1.0111x over previous
#include <cuda_runtime.h>
#include <cuda_fp16.h>
#include <cstdint>

// out[h,n,t] = q·k_quant^T + (qG/R)·sign((k_orig-k_quant)G)^T
// Single-pass fp16 augmented GEMM, K = 192:
//   Q'[h,n,:] = [ fp16(q) , fp16((q@G)/R) ]
//   K'[h,t,:] = [ fp16(k_quant) , fp16(sign((k_orig-k_quant)@G)) ] (sign in fp32)

#define HH 32
#define NN 2048
#define TT 2048
#define DD 128
#define RR 64
#define KD 192

__device__ __align__(16) __half g_Qa[(size_t)HH * NN * KD];
__device__ __align__(16) __half g_Ka[(size_t)HH * TT * KD];

static __device__ __forceinline__ uint32_t smem_u32(const void* p) {
    uint32_t a;
    asm("{ .reg .u64 t; cvta.to.shared.u64 t, %1; cvt.u32.u64 %0, t; }"
        : "=r"(a) : "l"(p));
    return a;
}

static __device__ __forceinline__ void cp16(uint32_t d, const void* s) {
    asm volatile("cp.async.cg.shared.global [%0], [%1], 16;" :: "r"(d), "l"(s) : "memory");
}

static __device__ __forceinline__ void ldsm4(uint32_t& r0, uint32_t& r1, uint32_t& r2,
                                             uint32_t& r3, uint32_t a) {
    asm volatile("ldmatrix.sync.aligned.m8n8.x4.shared.b16 {%0,%1,%2,%3}, [%4];"
                 : "=r"(r0), "=r"(r1), "=r"(r2), "=r"(r3) : "r"(a));
}

static __device__ __forceinline__ void mma16816(float* c, const uint32_t* a, const uint32_t* b) {
    asm volatile(
        "mma.sync.aligned.m16n8k16.row.col.f32.f16.f16.f32 "
        "{%0,%1,%2,%3}, {%4,%5,%6,%7}, {%8,%9}, {%0,%1,%2,%3};"
        : "+f"(c[0]), "+f"(c[1]), "+f"(c[2]), "+f"(c[3])
        : "r"(a[0]), "r"(a[1]), "r"(a[2]), "r"(a[3]), "r"(b[0]), "r"(b[1]));
}

static __device__ __forceinline__ uint32_t pack_h2(__half a, __half b) {
    __half2 t = __halves2half2(a, b);
    return *reinterpret_cast<uint32_t*>(&t);
}

// ---------------------------------------------------------------------------
// Fused prep: blocks [0,2048) do Q rows, [2048,4096) do K rows.
// ---------------------------------------------------------------------------
__global__ __launch_bounds__(256) void prep_all(const float* __restrict__ q,
                                                const float* __restrict__ k_orig,
                                                const float* __restrict__ k_quant,
                                                const float* __restrict__ G) {
    __shared__ float Gs[DD * RR];
    __shared__ float Es[32][DD];
    const int tid = threadIdx.x;
    const bool isQ = blockIdx.x < 2048;

    const float4* G4 = (const float4*)G;
    float4* Gs4 = (float4*)Gs;
    #pragma unroll
    for (int i = tid; i < DD * RR / 4; i += 256) Gs4[i] = G4[i];

    const size_t row0 = (size_t)(isQ ? blockIdx.x : (blockIdx.x - 2048)) * 32;
    __half* dst = isQ ? g_Qa : g_Ka;

    if (isQ) {
        #pragma unroll
        for (int i = tid; i < 32 * 32; i += 256) {
            int r = i >> 5, c = i & 31;
            float4 v = *(const float4*)(q + (row0 + r) * DD + c * 4);
            *(float4*)(&Es[r][c * 4]) = v;
            size_t o = (row0 + r) * KD + c * 4;
            *(uint2*)(&dst[o]) = make_uint2(
                pack_h2(__float2half_rn(v.x), __float2half_rn(v.y)),
                pack_h2(__float2half_rn(v.z), __float2half_rn(v.w)));
        }
    } else {
        #pragma unroll
        for (int i = tid; i < 32 * 32; i += 256) {
            int r = i >> 5, c = i & 31;
            float4 vq = *(const float4*)(k_quant + (row0 + r) * DD + c * 4);
            float4 vo = *(const float4*)(k_orig + (row0 + r) * DD + c * 4);
            float4 e4;
            e4.x = vo.x - vq.x; e4.y = vo.y - vq.y;
            e4.z = vo.z - vq.z; e4.w = vo.w - vq.w;
            *(float4*)(&Es[r][c * 4]) = e4;
            size_t o = (row0 + r) * KD + c * 4;
            *(uint2*)(&dst[o]) = make_uint2(
                pack_h2(__float2half_rn(vq.x), __float2half_rn(vq.y)),
                pack_h2(__float2half_rn(vq.z), __float2half_rn(vq.w)));
        }
    }
    __syncthreads();

    const int w = tid >> 5, lane = tid & 31;
    const int r0 = w * 4;
    float a0[4] = {0.f, 0.f, 0.f, 0.f}, a1[4] = {0.f, 0.f, 0.f, 0.f};
    #pragma unroll 4
    for (int d = 0; d < DD; ++d) {
        float gA = Gs[d * RR + lane];
        float gB = Gs[d * RR + 32 + lane];
        #pragma unroll
        for (int j = 0; j < 4; ++j) {
            float e = Es[r0 + j][d];
            a0[j] += e * gA;
            a1[j] += e * gB;
        }
    }
    if (isQ) {
        const float sc = 1.0f / (float)RR;
        #pragma unroll
        for (int j = 0; j < 4; ++j) {
            size_t o = (row0 + r0 + j) * KD + DD;
            dst[o + lane]      = __float2half_rn(a0[j] * sc);
            dst[o + 32 + lane] = __float2half_rn(a1[j] * sc);
        }
    } else {
        #pragma unroll
        for (int j = 0; j < 4; ++j) {
            float s0 = (a0[j] > 0.f) ? 1.f : ((a0[j] < 0.f) ? -1.f : 0.f);
            float s1 = (a1[j] > 0.f) ? 1.f : ((a1[j] < 0.f) ? -1.f : 0.f);
            size_t o = (row0 + r0 + j) * KD + DD;
            dst[o + lane]      = __float2half_rn(s0);
            dst[o + 32 + lane] = __float2half_rn(s1);
        }
    }
}

// ---------------------------------------------------------------------------
// HMMA GEMM: CTA tile 128(M) x 256(N), 512 threads (16 warps, 4/SMSP),
// warp tile 64x32. K: 12 steps of 16 fp16. 4-stage cp.async pipeline.
// 48B-padded smem rows (conflict-free ldmatrix).
// ---------------------------------------------------------------------------
#define A_BYTES 6144              // 128 rows * 48B
#define STAGE   18432             // A 6KB + B 12KB
#define SMEM_TOTAL (STAGE * 4)    // 73728
#define KSTEPS  12

__global__ __launch_bounds__(512) void gemm_hmma(float* __restrict__ C) {
    extern __shared__ char sm[];
    const uint32_t smb = smem_u32(sm);
    const int tid = threadIdx.x, lane = tid & 31, wid = tid >> 5;
    const int wm = wid & 1;        // 0..1  -> 64-row m slot
    const int wn = wid >> 1;       // 0..7  -> 32-col n slot

    const size_t arow0 = (size_t)blockIdx.z * NN + (size_t)blockIdx.y * 128;
    const size_t brow0 = (size_t)blockIdx.z * TT + (size_t)blockIdx.x * 256;

    auto loadStage = [&](int kk) {
        const int c0 = kk * 16;
        const uint32_t sA = smb + (kk & 3) * STAGE;
        const uint32_t sB = sA + A_BYTES;
        if (tid < 256) {           // A: 128 rows x 2 chunks
            int r = tid >> 1, c = tid & 1;
            const char* src = (const char*)(g_Qa + (arow0 + r) * KD + c0) + c * 16;
            cp16(sA + r * 48 + c * 16, src);
        }
        {                          // B: 256 rows x 2 chunks
            int r = tid >> 1, c = tid & 1;
            const char* src = (const char*)(g_Ka + (brow0 + r) * KD + c0) + c * 16;
            cp16(sB + r * 48 + c * 16, src);
        }
        asm volatile("cp.async.commit_group;" ::: "memory");
    };

    float acc[4][4][4];
    #pragma unroll
    for (int i = 0; i < 4; ++i)
        #pragma unroll
        for (int j = 0; j < 4; ++j)
            #pragma unroll
            for (int v = 0; v < 4; ++v) acc[i][j][v] = 0.f;

    loadStage(0);
    loadStage(1);
    loadStage(2);

    const uint32_t aB = smb + (uint32_t)(wm * 64 + (lane & 15)) * 48 + (lane >> 4) * 16;
    const uint32_t bB = smb + A_BYTES + (uint32_t)(wn * 32 + (lane & 15)) * 48 + (lane >> 4) * 16;

    #pragma unroll 1
    for (int kk = 0; kk < KSTEPS; ++kk) {
        asm volatile("cp.async.wait_group 2;" ::: "memory");
        __syncthreads();
        if (kk + 3 < KSTEPS) loadStage(kk + 3);
        else asm volatile("cp.async.commit_group;" ::: "memory");

        const uint32_t so = (kk & 3) * STAGE;
        uint32_t a[4][4];
        #pragma unroll
        for (int mt = 0; mt < 4; ++mt)
            ldsm4(a[mt][0], a[mt][1], a[mt][2], a[mt][3], aB + so + mt * (16 * 48));
        uint32_t b[4][2];
        #pragma unroll
        for (int nb = 0; nb < 2; ++nb) {
            uint32_t r0, r1, r2, r3;
            ldsm4(r0, r1, r2, r3, bB + so + nb * (16 * 48));
            b[2 * nb][0] = r0; b[2 * nb][1] = r2;
            b[2 * nb + 1][0] = r1; b[2 * nb + 1][1] = r3;
        }
        #pragma unroll
        for (int mt = 0; mt < 4; ++mt)
            #pragma unroll
            for (int nt = 0; nt < 4; ++nt)
                mma16816(acc[mt][nt], a[mt], b[nt]);
    }

    // Epilogue: streaming stores (C never re-read)
    float* Cb = C + ((size_t)blockIdx.z * NN + (size_t)blockIdx.y * 128 + wm * 64) * TT
                  + (size_t)blockIdx.x * 256 + wn * 32;
    const int r = lane >> 2, cc = (lane & 3) * 2;
    #pragma unroll
    for (int mt = 0; mt < 4; ++mt) {
        #pragma unroll
        for (int nt = 0; nt < 4; ++nt) {
            float2 v0 = make_float2(acc[mt][nt][0], acc[mt][nt][1]);
            float2 v1 = make_float2(acc[mt][nt][2], acc[mt][nt][3]);
            __stcs((float2*)(Cb + (size_t)(mt * 16 + r) * TT + nt * 8 + cc), v0);
            __stcs((float2*)(Cb + (size_t)(mt * 16 + r + 8) * TT + nt * 8 + cc), v1);
        }
    }
}

// ---------------------------------------------------------------------------
extern "C" void kernel_launch(void* const* d_in, const int* in_sizes, int n_in,
                              void* d_out, int out_size) {
    const float* q       = (const float*)d_in[0];
    const float* k_orig  = (const float*)d_in[1];
    const float* k_quant = (const float*)d_in[2];
    const float* G       = (const float*)d_in[3];
    float* out = (float*)d_out;

    cudaFuncSetAttribute(gemm_hmma, cudaFuncAttributeMaxDynamicSharedMemorySize, SMEM_TOTAL);

    prep_all<<<4096, 256>>>(q, k_orig, k_quant, G);

    dim3 grid(TT / 256, NN / 128, HH);
    gemm_hmma<<<grid, 512, SMEM_TOTAL>>>(out);
}

// round 9
// speedup vs baseline: 3.9136x; 1.2287x over previous
#include <cuda_runtime.h>
#include <cuda_fp16.h>
#include <cstdint>

// out[h,n,t] = q·k_quant^T + (qG/R)·sign((k_orig-k_quant)G)^T
// Single-pass fp16 augmented GEMM, K = 192:
//   Q'[h,n,:] = [ fp16(q) , fp16((q@G)/R) ]
//   K'[h,t,:] = [ fp16(k_quant) , fp16(sign((k_orig-k_quant)@G)) ] (sign in fp32)

#define HH 32
#define NN 2048
#define TT 2048
#define DD 128
#define RR 64
#define KD 192

__device__ __align__(16) __half g_Qa[(size_t)HH * NN * KD];
__device__ __align__(16) __half g_Ka[(size_t)HH * TT * KD];

static __device__ __forceinline__ uint32_t smem_u32(const void* p) {
    uint32_t a;
    asm("{ .reg .u64 t; cvta.to.shared.u64 t, %1; cvt.u32.u64 %0, t; }"
        : "=r"(a) : "l"(p));
    return a;
}

static __device__ __forceinline__ void cp16(uint32_t d, const void* s) {
    asm volatile("cp.async.cg.shared.global [%0], [%1], 16;" :: "r"(d), "l"(s) : "memory");
}

static __device__ __forceinline__ void ldsm4(uint32_t& r0, uint32_t& r1, uint32_t& r2,
                                             uint32_t& r3, uint32_t a) {
    asm volatile("ldmatrix.sync.aligned.m8n8.x4.shared.b16 {%0,%1,%2,%3}, [%4];"
                 : "=r"(r0), "=r"(r1), "=r"(r2), "=r"(r3) : "r"(a));
}

static __device__ __forceinline__ void mma16816(float* c, const uint32_t* a, const uint32_t* b) {
    asm volatile(
        "mma.sync.aligned.m16n8k16.row.col.f32.f16.f16.f32 "
        "{%0,%1,%2,%3}, {%4,%5,%6,%7}, {%8,%9}, {%0,%1,%2,%3};"
        : "+f"(c[0]), "+f"(c[1]), "+f"(c[2]), "+f"(c[3])
        : "r"(a[0]), "r"(a[1]), "r"(a[2]), "r"(a[3]), "r"(b[0]), "r"(b[1]));
}

static __device__ __forceinline__ uint32_t pack_h2(__half a, __half b) {
    __half2 t = __halves2half2(a, b);
    return *reinterpret_cast<uint32_t*>(&t);
}

// ---------------------------------------------------------------------------
// Fused prep: blocks [0,2048) do Q rows, [2048,4096) do K rows.
// ---------------------------------------------------------------------------
__global__ __launch_bounds__(256) void prep_all(const float* __restrict__ q,
                                                const float* __restrict__ k_orig,
                                                const float* __restrict__ k_quant,
                                                const float* __restrict__ G) {
    __shared__ float Gs[DD * RR];
    __shared__ float Es[32][DD];
    const int tid = threadIdx.x;
    const bool isQ = blockIdx.x < 2048;

    const float4* G4 = (const float4*)G;
    float4* Gs4 = (float4*)Gs;
    #pragma unroll
    for (int i = tid; i < DD * RR / 4; i += 256) Gs4[i] = G4[i];

    const size_t row0 = (size_t)(isQ ? blockIdx.x : (blockIdx.x - 2048)) * 32;
    __half* dst = isQ ? g_Qa : g_Ka;

    if (isQ) {
        #pragma unroll
        for (int i = tid; i < 32 * 32; i += 256) {
            int r = i >> 5, c = i & 31;
            float4 v = *(const float4*)(q + (row0 + r) * DD + c * 4);
            *(float4*)(&Es[r][c * 4]) = v;
            size_t o = (row0 + r) * KD + c * 4;
            *(uint2*)(&dst[o]) = make_uint2(
                pack_h2(__float2half_rn(v.x), __float2half_rn(v.y)),
                pack_h2(__float2half_rn(v.z), __float2half_rn(v.w)));
        }
    } else {
        #pragma unroll
        for (int i = tid; i < 32 * 32; i += 256) {
            int r = i >> 5, c = i & 31;
            float4 vq = *(const float4*)(k_quant + (row0 + r) * DD + c * 4);
            float4 vo = *(const float4*)(k_orig + (row0 + r) * DD + c * 4);
            float4 e4;
            e4.x = vo.x - vq.x; e4.y = vo.y - vq.y;
            e4.z = vo.z - vq.z; e4.w = vo.w - vq.w;
            *(float4*)(&Es[r][c * 4]) = e4;
            size_t o = (row0 + r) * KD + c * 4;
            *(uint2*)(&dst[o]) = make_uint2(
                pack_h2(__float2half_rn(vq.x), __float2half_rn(vq.y)),
                pack_h2(__float2half_rn(vq.z), __float2half_rn(vq.w)));
        }
    }
    __syncthreads();

    const int w = tid >> 5, lane = tid & 31;
    const int r0 = w * 4;
    float a0[4] = {0.f, 0.f, 0.f, 0.f}, a1[4] = {0.f, 0.f, 0.f, 0.f};
    #pragma unroll 4
    for (int d = 0; d < DD; ++d) {
        float gA = Gs[d * RR + lane];
        float gB = Gs[d * RR + 32 + lane];
        #pragma unroll
        for (int j = 0; j < 4; ++j) {
            float e = Es[r0 + j][d];
            a0[j] += e * gA;
            a1[j] += e * gB;
        }
    }
    if (isQ) {
        const float sc = 1.0f / (float)RR;
        #pragma unroll
        for (int j = 0; j < 4; ++j) {
            size_t o = (row0 + r0 + j) * KD + DD;
            dst[o + lane]      = __float2half_rn(a0[j] * sc);
            dst[o + 32 + lane] = __float2half_rn(a1[j] * sc);
        }
    } else {
        #pragma unroll
        for (int j = 0; j < 4; ++j) {
            float s0 = (a0[j] > 0.f) ? 1.f : ((a0[j] < 0.f) ? -1.f : 0.f);
            float s1 = (a1[j] > 0.f) ? 1.f : ((a1[j] < 0.f) ? -1.f : 0.f);
            size_t o = (row0 + r0 + j) * KD + DD;
            dst[o + lane]      = __float2half_rn(s0);
            dst[o + 32 + lane] = __float2half_rn(s1);
        }
    }
}

// ---------------------------------------------------------------------------
// HMMA GEMM: CTA tile 128(M) x 256(N), 512 threads (16 warps), warp tile 64x32.
// All of K (192 cols) staged in smem as 3 stages of 64 cols, loaded up-front
// as 3 cp.async groups -> only 3 sync points in the whole kernel.
// Rows padded to 144B (stride 9 x 16B, 9==1 mod 8 -> conflict-free ldmatrix).
// ---------------------------------------------------------------------------
#define ROWB 144
#define A_BYTES (128 * ROWB)              // 18432
#define STAGE (A_BYTES + 256 * ROWB)      // 55296
#define SMEM_TOTAL (STAGE * 3)            // 165888
#define B_OFF A_BYTES

__global__ __launch_bounds__(512) void gemm_hmma(float* __restrict__ C) {
    extern __shared__ char sm[];
    const uint32_t smb = smem_u32(sm);
    const int tid = threadIdx.x, lane = tid & 31, wid = tid >> 5;
    const int wm = wid & 1;        // 0..1  -> 64-row m slot
    const int wn = wid >> 1;       // 0..7  -> 32-col n slot

    const size_t arow0 = (size_t)blockIdx.z * NN + (size_t)blockIdx.y * 128;
    const size_t brow0 = (size_t)blockIdx.z * TT + (size_t)blockIdx.x * 256;

    // issue all three stage loads up-front (one commit group per stage)
    #pragma unroll
    for (int s = 0; s < 3; ++s) {
        const uint32_t sA = smb + s * STAGE;
        const uint32_t sB = sA + B_OFF;
        // A: 128 rows x 8 chunks of 16B = 1024 chunks -> 2 per thread
        #pragma unroll
        for (int i = 0; i < 2; ++i) {
            int u = tid + (i << 9);
            int r = u >> 3, c = u & 7;
            cp16(sA + r * ROWB + c * 16,
                 (const char*)(g_Qa + (arow0 + r) * KD + s * 64) + c * 16);
        }
        // B: 256 rows x 8 chunks = 2048 chunks -> 4 per thread
        #pragma unroll
        for (int i = 0; i < 4; ++i) {
            int u = tid + (i << 9);
            int r = u >> 3, c = u & 7;
            cp16(sB + r * ROWB + c * 16,
                 (const char*)(g_Ka + (brow0 + r) * KD + s * 64) + c * 16);
        }
        asm volatile("cp.async.commit_group;" ::: "memory");
    }

    float acc[4][4][4];
    #pragma unroll
    for (int i = 0; i < 4; ++i)
        #pragma unroll
        for (int j = 0; j < 4; ++j)
            #pragma unroll
            for (int v = 0; v < 4; ++v) acc[i][j][v] = 0.f;

    const uint32_t aB = smb + (uint32_t)(wm * 64 + (lane & 15)) * ROWB + (lane >> 4) * 16;
    const uint32_t bB = smb + B_OFF + (uint32_t)(wn * 32 + (lane & 15)) * ROWB + (lane >> 4) * 16;

    #pragma unroll
    for (int s = 0; s < 3; ++s) {
        if (s == 0)      asm volatile("cp.async.wait_group 2;" ::: "memory");
        else if (s == 1) asm volatile("cp.async.wait_group 1;" ::: "memory");
        else             asm volatile("cp.async.wait_group 0;" ::: "memory");
        __syncthreads();

        const uint32_t so = s * STAGE;
        #pragma unroll
        for (int kc = 0; kc < 4; ++kc) {     // 4 k16 chunks within the 64-col stage
            uint32_t a[4][4];
            #pragma unroll
            for (int mt = 0; mt < 4; ++mt)
                ldsm4(a[mt][0], a[mt][1], a[mt][2], a[mt][3],
                      aB + so + kc * 32 + mt * (16 * ROWB));
            uint32_t b[4][2];
            #pragma unroll
            for (int nb = 0; nb < 2; ++nb) {
                uint32_t r0, r1, r2, r3;
                ldsm4(r0, r1, r2, r3, bB + so + kc * 32 + nb * (16 * ROWB));
                b[2 * nb][0] = r0; b[2 * nb][1] = r2;
                b[2 * nb + 1][0] = r1; b[2 * nb + 1][1] = r3;
            }
            #pragma unroll
            for (int mt = 0; mt < 4; ++mt)
                #pragma unroll
                for (int nt = 0; nt < 4; ++nt)
                    mma16816(acc[mt][nt], a[mt], b[nt]);
        }
    }

    // Epilogue: streaming stores (C never re-read)
    float* Cb = C + ((size_t)blockIdx.z * NN + (size_t)blockIdx.y * 128 + wm * 64) * TT
                  + (size_t)blockIdx.x * 256 + wn * 32;
    const int r = lane >> 2, cc = (lane & 3) * 2;
    #pragma unroll
    for (int mt = 0; mt < 4; ++mt) {
        #pragma unroll
        for (int nt = 0; nt < 4; ++nt) {
            float2 v0 = make_float2(acc[mt][nt][0], acc[mt][nt][1]);
            float2 v1 = make_float2(acc[mt][nt][2], acc[mt][nt][3]);
            __stcs((float2*)(Cb + (size_t)(mt * 16 + r) * TT + nt * 8 + cc), v0);
            __stcs((float2*)(Cb + (size_t)(mt * 16 + r + 8) * TT + nt * 8 + cc), v1);
        }
    }
}

// ---------------------------------------------------------------------------
extern "C" void kernel_launch(void* const* d_in, const int* in_sizes, int n_in,
                              void* d_out, int out_size) {
    const float* q       = (const float*)d_in[0];
    const float* k_orig  = (const float*)d_in[1];
    const float* k_quant = (const float*)d_in[2];
    const float* G       = (const float*)d_in[3];
    float* out = (float*)d_out;

    cudaFuncSetAttribute(gemm_hmma, cudaFuncAttributeMaxDynamicSharedMemorySize, SMEM_TOTAL);

    prep_all<<<4096, 256>>>(q, k_orig, k_quant, G);

    dim3 grid(TT / 256, NN / 128, HH);
    gemm_hmma<<<grid, 512, SMEM_TOTAL>>>(out);
}

// round 10
// speedup vs baseline: 3.9908x; 1.0197x over previous
#include <cuda_runtime.h>
#include <cuda_fp16.h>
#include <cstdint>

// out[h,n,t] = q·k_quant^T + (qG/R)·sign((k_orig-k_quant)G)^T
// Single-pass fp16 augmented GEMM, K = 192:
//   Q'[h,n,:] = [ fp16(q) , fp16((q@G)/R) ]
//   K'[h,t,:] = [ fp16(k_quant) , fp16(sign((k_orig-k_quant)@G)) ] (sign in fp32)
// Persistent-CTA GEMM: one CTA per SM, rolling 3-slot cp.async ring across
// the whole tile stream (no pipeline drain at tile boundaries).

#define HH 32
#define NN 2048
#define TT 2048
#define DD 128
#define RR 64
#define KD 192
#define NTILES 4096   // 32 heads * 16 m-tiles * 8 n-tiles

__device__ __align__(16) __half g_Qa[(size_t)HH * NN * KD];
__device__ __align__(16) __half g_Ka[(size_t)HH * TT * KD];

static __device__ __forceinline__ uint32_t smem_u32(const void* p) {
    uint32_t a;
    asm("{ .reg .u64 t; cvta.to.shared.u64 t, %1; cvt.u32.u64 %0, t; }"
        : "=r"(a) : "l"(p));
    return a;
}

static __device__ __forceinline__ void cp16(uint32_t d, const void* s) {
    asm volatile("cp.async.cg.shared.global [%0], [%1], 16;" :: "r"(d), "l"(s) : "memory");
}

static __device__ __forceinline__ void ldsm4(uint32_t& r0, uint32_t& r1, uint32_t& r2,
                                             uint32_t& r3, uint32_t a) {
    asm volatile("ldmatrix.sync.aligned.m8n8.x4.shared.b16 {%0,%1,%2,%3}, [%4];"
                 : "=r"(r0), "=r"(r1), "=r"(r2), "=r"(r3) : "r"(a));
}

static __device__ __forceinline__ void mma16816(float* c, const uint32_t* a, const uint32_t* b) {
    asm volatile(
        "mma.sync.aligned.m16n8k16.row.col.f32.f16.f16.f32 "
        "{%0,%1,%2,%3}, {%4,%5,%6,%7}, {%8,%9}, {%0,%1,%2,%3};"
        : "+f"(c[0]), "+f"(c[1]), "+f"(c[2]), "+f"(c[3])
        : "r"(a[0]), "r"(a[1]), "r"(a[2]), "r"(a[3]), "r"(b[0]), "r"(b[1]));
}

static __device__ __forceinline__ uint32_t pack_h2(__half a, __half b) {
    __half2 t = __halves2half2(a, b);
    return *reinterpret_cast<uint32_t*>(&t);
}

// ---------------------------------------------------------------------------
// Fused prep: blocks [0,2048) do Q rows, [2048,4096) do K rows.
// ---------------------------------------------------------------------------
__global__ __launch_bounds__(256) void prep_all(const float* __restrict__ q,
                                                const float* __restrict__ k_orig,
                                                const float* __restrict__ k_quant,
                                                const float* __restrict__ G) {
    __shared__ float Gs[DD * RR];
    __shared__ float Es[32][DD];
    const int tid = threadIdx.x;
    const bool isQ = blockIdx.x < 2048;

    const float4* G4 = (const float4*)G;
    float4* Gs4 = (float4*)Gs;
    #pragma unroll
    for (int i = tid; i < DD * RR / 4; i += 256) Gs4[i] = G4[i];

    const size_t row0 = (size_t)(isQ ? blockIdx.x : (blockIdx.x - 2048)) * 32;
    __half* dst = isQ ? g_Qa : g_Ka;

    if (isQ) {
        #pragma unroll
        for (int i = tid; i < 32 * 32; i += 256) {
            int r = i >> 5, c = i & 31;
            float4 v = *(const float4*)(q + (row0 + r) * DD + c * 4);
            *(float4*)(&Es[r][c * 4]) = v;
            size_t o = (row0 + r) * KD + c * 4;
            *(uint2*)(&dst[o]) = make_uint2(
                pack_h2(__float2half_rn(v.x), __float2half_rn(v.y)),
                pack_h2(__float2half_rn(v.z), __float2half_rn(v.w)));
        }
    } else {
        #pragma unroll
        for (int i = tid; i < 32 * 32; i += 256) {
            int r = i >> 5, c = i & 31;
            float4 vq = *(const float4*)(k_quant + (row0 + r) * DD + c * 4);
            float4 vo = *(const float4*)(k_orig + (row0 + r) * DD + c * 4);
            float4 e4;
            e4.x = vo.x - vq.x; e4.y = vo.y - vq.y;
            e4.z = vo.z - vq.z; e4.w = vo.w - vq.w;
            *(float4*)(&Es[r][c * 4]) = e4;
            size_t o = (row0 + r) * KD + c * 4;
            *(uint2*)(&dst[o]) = make_uint2(
                pack_h2(__float2half_rn(vq.x), __float2half_rn(vq.y)),
                pack_h2(__float2half_rn(vq.z), __float2half_rn(vq.w)));
        }
    }
    __syncthreads();

    const int w = tid >> 5, lane = tid & 31;
    const int r0 = w * 4;
    float a0[4] = {0.f, 0.f, 0.f, 0.f}, a1[4] = {0.f, 0.f, 0.f, 0.f};
    #pragma unroll 4
    for (int d = 0; d < DD; ++d) {
        float gA = Gs[d * RR + lane];
        float gB = Gs[d * RR + 32 + lane];
        #pragma unroll
        for (int j = 0; j < 4; ++j) {
            float e = Es[r0 + j][d];
            a0[j] += e * gA;
            a1[j] += e * gB;
        }
    }
    if (isQ) {
        const float sc = 1.0f / (float)RR;
        #pragma unroll
        for (int j = 0; j < 4; ++j) {
            size_t o = (row0 + r0 + j) * KD + DD;
            dst[o + lane]      = __float2half_rn(a0[j] * sc);
            dst[o + 32 + lane] = __float2half_rn(a1[j] * sc);
        }
    } else {
        #pragma unroll
        for (int j = 0; j < 4; ++j) {
            float s0 = (a0[j] > 0.f) ? 1.f : ((a0[j] < 0.f) ? -1.f : 0.f);
            float s1 = (a1[j] > 0.f) ? 1.f : ((a1[j] < 0.f) ? -1.f : 0.f);
            size_t o = (row0 + r0 + j) * KD + DD;
            dst[o + lane]      = __float2half_rn(s0);
            dst[o + 32 + lane] = __float2half_rn(s1);
        }
    }
}

// ---------------------------------------------------------------------------
// Persistent HMMA GEMM. CTA tile 128(M) x 256(N), 512 threads, warp 64x32.
// Chunk stream: chunk c -> (tile c/3, stage c%3); smem slot = c%3.
// Protocol per chunk: wait_group 1 (chunk c landed) -> syncthreads (slot of
// c-1 free + visibility) -> issue chunk c+2 into that slot -> compute.
// Rows padded to 144B (stride 9, conflict-free ldmatrix).
// ---------------------------------------------------------------------------
#define ROWB 144
#define A_BYTES (128 * ROWB)              // 18432
#define STAGE (A_BYTES + 256 * ROWB)      // 55296
#define SMEM_TOTAL (STAGE * 3)            // 165888
#define B_OFF A_BYTES

__global__ __launch_bounds__(512) void gemm_persist(float* __restrict__ C) {
    extern __shared__ char sm[];
    const uint32_t smb = smem_u32(sm);
    const int tid = threadIdx.x, lane = tid & 31, wid = tid >> 5;
    const int wm = wid & 1;        // 0..1 -> 64-row m slot
    const int wn = wid >> 1;       // 0..7 -> 32-col n slot
    const int bid = blockIdx.x, grid = gridDim.x;

    const int myTiles = (bid < NTILES) ? ((NTILES - 1 - bid) / grid + 1) : 0;
    const int myChunks = myTiles * 3;
    if (myChunks == 0) return;

    auto issueChunk = [&](int c2) {
        const int t = c2 / 3, s = c2 - t * 3;
        const int tileIdx = bid + t * grid;
        const int h = tileIdx >> 7, rem = tileIdx & 127;
        const size_t arow0 = (size_t)h * NN + (size_t)(rem >> 3) * 128;
        const size_t brow0 = (size_t)h * TT + (size_t)(rem & 7) * 256;
        const uint32_t sA = smb + s * STAGE;
        const uint32_t sB = sA + B_OFF;
        const int c0 = s * 64;
        #pragma unroll
        for (int i = 0; i < 2; ++i) {         // A: 1024 16B chunks
            int u = tid + (i << 9);
            int r = u >> 3, cc = u & 7;
            cp16(sA + r * ROWB + cc * 16,
                 (const char*)(g_Qa + (arow0 + r) * KD + c0) + cc * 16);
        }
        #pragma unroll
        for (int i = 0; i < 4; ++i) {         // B: 2048 16B chunks
            int u = tid + (i << 9);
            int r = u >> 3, cc = u & 7;
            cp16(sB + r * ROWB + cc * 16,
                 (const char*)(g_Ka + (brow0 + r) * KD + c0) + cc * 16);
        }
        asm volatile("cp.async.commit_group;" ::: "memory");
    };

    float acc[4][4][4];
    #pragma unroll
    for (int i = 0; i < 4; ++i)
        #pragma unroll
        for (int j = 0; j < 4; ++j)
            #pragma unroll
            for (int v = 0; v < 4; ++v) acc[i][j][v] = 0.f;

    issueChunk(0);
    if (myChunks > 1) issueChunk(1);

    const uint32_t aB = smb + (uint32_t)(wm * 64 + (lane & 15)) * ROWB + (lane >> 4) * 16;
    const uint32_t bB = smb + B_OFF + (uint32_t)(wn * 32 + (lane & 15)) * ROWB + (lane >> 4) * 16;

    #pragma unroll 1
    for (int c = 0; c < myChunks; ++c) {
        const int t = c / 3, s = c - t * 3;

        if (c + 1 < myChunks) asm volatile("cp.async.wait_group 1;" ::: "memory");
        else                  asm volatile("cp.async.wait_group 0;" ::: "memory");
        __syncthreads();                     // data of chunk c visible; slot of c-1 free
        if (c + 2 < myChunks) issueChunk(c + 2);

        const uint32_t so = s * STAGE;
        #pragma unroll
        for (int kc = 0; kc < 4; ++kc) {
            uint32_t a[4][4];
            #pragma unroll
            for (int mt = 0; mt < 4; ++mt)
                ldsm4(a[mt][0], a[mt][1], a[mt][2], a[mt][3],
                      aB + so + kc * 32 + mt * (16 * ROWB));
            uint32_t b[4][2];
            #pragma unroll
            for (int nb = 0; nb < 2; ++nb) {
                uint32_t r0, r1, r2, r3;
                ldsm4(r0, r1, r2, r3, bB + so + kc * 32 + nb * (16 * ROWB));
                b[2 * nb][0] = r0; b[2 * nb][1] = r2;
                b[2 * nb + 1][0] = r1; b[2 * nb + 1][1] = r3;
            }
            #pragma unroll
            for (int mt = 0; mt < 4; ++mt)
                #pragma unroll
                for (int nt = 0; nt < 4; ++nt)
                    mma16816(acc[mt][nt], a[mt], b[nt]);
        }

        if (s == 2) {
            // epilogue for this tile; overlaps with in-flight loads of next tile
            const int tileIdx = bid + t * grid;
            const int h = tileIdx >> 7, rem = tileIdx & 127;
            float* Cb = C + ((size_t)h * NN + (size_t)(rem >> 3) * 128 + wm * 64) * TT
                          + (size_t)(rem & 7) * 256 + wn * 32;
            const int r = lane >> 2, cc = (lane & 3) * 2;
            #pragma unroll
            for (int mt = 0; mt < 4; ++mt) {
                #pragma unroll
                for (int nt = 0; nt < 4; ++nt) {
                    float2 v0 = make_float2(acc[mt][nt][0], acc[mt][nt][1]);
                    float2 v1 = make_float2(acc[mt][nt][2], acc[mt][nt][3]);
                    __stcs((float2*)(Cb + (size_t)(mt * 16 + r) * TT + nt * 8 + cc), v0);
                    __stcs((float2*)(Cb + (size_t)(mt * 16 + r + 8) * TT + nt * 8 + cc), v1);
                    acc[mt][nt][0] = 0.f; acc[mt][nt][1] = 0.f;
                    acc[mt][nt][2] = 0.f; acc[mt][nt][3] = 0.f;
                }
            }
        }
    }
}

// ---------------------------------------------------------------------------
extern "C" void kernel_launch(void* const* d_in, const int* in_sizes, int n_in,
                              void* d_out, int out_size) {
    const float* q       = (const float*)d_in[0];
    const float* k_orig  = (const float*)d_in[1];
    const float* k_quant = (const float*)d_in[2];
    const float* G       = (const float*)d_in[3];
    float* out = (float*)d_out;

    int dev = 0, nsm = 148;
    cudaGetDevice(&dev);
    cudaDeviceGetAttribute(&nsm, cudaDevAttrMultiProcessorCount, dev);

    cudaFuncSetAttribute(gemm_persist, cudaFuncAttributeMaxDynamicSharedMemorySize, SMEM_TOTAL);

    prep_all<<<4096, 256>>>(q, k_orig, k_quant, G);
    gemm_persist<<<nsm, 512, SMEM_TOTAL>>>(out);
}

// round 11
// speedup vs baseline: 4.0336x; 1.0107x over previous
#include <cuda_runtime.h>
#include <cuda_fp16.h>
#include <cstdint>

// out[h,n,t] = q·k_quant^T + (qG/R)·sign((k_orig-k_quant)G)^T
// Single-pass fp16 augmented GEMM, K = 192:
//   Q'[h,n,:] = [ fp16(q) , fp16((q@G)/R) ]
//   K'[h,t,:] = [ fp16(k_quant) , fp16(sign((k_orig-k_quant)@G)) ] (sign in fp32)
// Persistent-CTA GEMM, rolling 3-slot cp.async ring, register double-buffered
// ldmatrix fragments (LDSM of kc+1 overlaps HMMA of kc).

#define HH 32
#define NN 2048
#define TT 2048
#define DD 128
#define RR 64
#define KD 192
#define NTILES 4096   // 32 heads * 16 m-tiles * 8 n-tiles

__device__ __align__(16) __half g_Qa[(size_t)HH * NN * KD];
__device__ __align__(16) __half g_Ka[(size_t)HH * TT * KD];

static __device__ __forceinline__ uint32_t smem_u32(const void* p) {
    uint32_t a;
    asm("{ .reg .u64 t; cvta.to.shared.u64 t, %1; cvt.u32.u64 %0, t; }"
        : "=r"(a) : "l"(p));
    return a;
}

static __device__ __forceinline__ void cp16(uint32_t d, const void* s) {
    asm volatile("cp.async.cg.shared.global [%0], [%1], 16;" :: "r"(d), "l"(s) : "memory");
}

static __device__ __forceinline__ void ldsm4(uint32_t& r0, uint32_t& r1, uint32_t& r2,
                                             uint32_t& r3, uint32_t a) {
    asm volatile("ldmatrix.sync.aligned.m8n8.x4.shared.b16 {%0,%1,%2,%3}, [%4];"
                 : "=r"(r0), "=r"(r1), "=r"(r2), "=r"(r3) : "r"(a));
}

static __device__ __forceinline__ void mma16816(float* c, const uint32_t* a, const uint32_t* b) {
    asm volatile(
        "mma.sync.aligned.m16n8k16.row.col.f32.f16.f16.f32 "
        "{%0,%1,%2,%3}, {%4,%5,%6,%7}, {%8,%9}, {%0,%1,%2,%3};"
        : "+f"(c[0]), "+f"(c[1]), "+f"(c[2]), "+f"(c[3])
        : "r"(a[0]), "r"(a[1]), "r"(a[2]), "r"(a[3]), "r"(b[0]), "r"(b[1]));
}

static __device__ __forceinline__ uint32_t pack_h2(__half a, __half b) {
    __half2 t = __halves2half2(a, b);
    return *reinterpret_cast<uint32_t*>(&t);
}

// ---------------------------------------------------------------------------
// Fused prep: blocks [0,2048) do Q rows, [2048,4096) do K rows.
// ---------------------------------------------------------------------------
__global__ __launch_bounds__(256) void prep_all(const float* __restrict__ q,
                                                const float* __restrict__ k_orig,
                                                const float* __restrict__ k_quant,
                                                const float* __restrict__ G) {
    __shared__ float Gs[DD * RR];
    __shared__ float Es[32][DD];
    const int tid = threadIdx.x;
    const bool isQ = blockIdx.x < 2048;

    const float4* G4 = (const float4*)G;
    float4* Gs4 = (float4*)Gs;
    #pragma unroll
    for (int i = tid; i < DD * RR / 4; i += 256) Gs4[i] = G4[i];

    const size_t row0 = (size_t)(isQ ? blockIdx.x : (blockIdx.x - 2048)) * 32;
    __half* dst = isQ ? g_Qa : g_Ka;

    if (isQ) {
        #pragma unroll
        for (int i = tid; i < 32 * 32; i += 256) {
            int r = i >> 5, c = i & 31;
            float4 v = *(const float4*)(q + (row0 + r) * DD + c * 4);
            *(float4*)(&Es[r][c * 4]) = v;
            size_t o = (row0 + r) * KD + c * 4;
            *(uint2*)(&dst[o]) = make_uint2(
                pack_h2(__float2half_rn(v.x), __float2half_rn(v.y)),
                pack_h2(__float2half_rn(v.z), __float2half_rn(v.w)));
        }
    } else {
        #pragma unroll
        for (int i = tid; i < 32 * 32; i += 256) {
            int r = i >> 5, c = i & 31;
            float4 vq = *(const float4*)(k_quant + (row0 + r) * DD + c * 4);
            float4 vo = *(const float4*)(k_orig + (row0 + r) * DD + c * 4);
            float4 e4;
            e4.x = vo.x - vq.x; e4.y = vo.y - vq.y;
            e4.z = vo.z - vq.z; e4.w = vo.w - vq.w;
            *(float4*)(&Es[r][c * 4]) = e4;
            size_t o = (row0 + r) * KD + c * 4;
            *(uint2*)(&dst[o]) = make_uint2(
                pack_h2(__float2half_rn(vq.x), __float2half_rn(vq.y)),
                pack_h2(__float2half_rn(vq.z), __float2half_rn(vq.w)));
        }
    }
    __syncthreads();

    const int w = tid >> 5, lane = tid & 31;
    const int r0 = w * 4;
    float a0[4] = {0.f, 0.f, 0.f, 0.f}, a1[4] = {0.f, 0.f, 0.f, 0.f};
    #pragma unroll 4
    for (int d = 0; d < DD; ++d) {
        float gA = Gs[d * RR + lane];
        float gB = Gs[d * RR + 32 + lane];
        #pragma unroll
        for (int j = 0; j < 4; ++j) {
            float e = Es[r0 + j][d];
            a0[j] += e * gA;
            a1[j] += e * gB;
        }
    }
    if (isQ) {
        const float sc = 1.0f / (float)RR;
        #pragma unroll
        for (int j = 0; j < 4; ++j) {
            size_t o = (row0 + r0 + j) * KD + DD;
            dst[o + lane]      = __float2half_rn(a0[j] * sc);
            dst[o + 32 + lane] = __float2half_rn(a1[j] * sc);
        }
    } else {
        #pragma unroll
        for (int j = 0; j < 4; ++j) {
            float s0 = (a0[j] > 0.f) ? 1.f : ((a0[j] < 0.f) ? -1.f : 0.f);
            float s1 = (a1[j] > 0.f) ? 1.f : ((a1[j] < 0.f) ? -1.f : 0.f);
            size_t o = (row0 + r0 + j) * KD + DD;
            dst[o + lane]      = __float2half_rn(s0);
            dst[o + 32 + lane] = __float2half_rn(s1);
        }
    }
}

// ---------------------------------------------------------------------------
// Persistent HMMA GEMM. CTA tile 128(M) x 256(N), 512 threads, warp 64x32.
// Chunk stream: chunk c -> (tile c/3, stage c%3); smem slot = c%3.
// Register double-buffered fragments: LDSM(kc+1) issued before MMA(kc).
// Rows padded to 144B (stride 9, conflict-free ldmatrix).
// ---------------------------------------------------------------------------
#define ROWB 144
#define A_BYTES (128 * ROWB)              // 18432
#define STAGE (A_BYTES + 256 * ROWB)      // 55296
#define SMEM_TOTAL (STAGE * 3)            // 165888
#define B_OFF A_BYTES

__global__ __launch_bounds__(512) void gemm_persist(float* __restrict__ C) {
    extern __shared__ char sm[];
    const uint32_t smb = smem_u32(sm);
    const int tid = threadIdx.x, lane = tid & 31, wid = tid >> 5;
    const int wm = wid & 1;        // 0..1 -> 64-row m slot
    const int wn = wid >> 1;       // 0..7 -> 32-col n slot
    const int bid = blockIdx.x, grid = gridDim.x;

    const int myTiles = (bid < NTILES) ? ((NTILES - 1 - bid) / grid + 1) : 0;
    const int myChunks = myTiles * 3;
    if (myChunks == 0) return;

    auto issueChunk = [&](int c2) {
        const int t = c2 / 3, s = c2 - t * 3;
        const int tileIdx = bid + t * grid;
        const int h = tileIdx >> 7, rem = tileIdx & 127;
        const size_t arow0 = (size_t)h * NN + (size_t)(rem >> 3) * 128;
        const size_t brow0 = (size_t)h * TT + (size_t)(rem & 7) * 256;
        const uint32_t sA = smb + s * STAGE;
        const uint32_t sB = sA + B_OFF;
        const int c0 = s * 64;
        #pragma unroll
        for (int i = 0; i < 2; ++i) {         // A: 1024 16B chunks
            int u = tid + (i << 9);
            int r = u >> 3, cc = u & 7;
            cp16(sA + r * ROWB + cc * 16,
                 (const char*)(g_Qa + (arow0 + r) * KD + c0) + cc * 16);
        }
        #pragma unroll
        for (int i = 0; i < 4; ++i) {         // B: 2048 16B chunks
            int u = tid + (i << 9);
            int r = u >> 3, cc = u & 7;
            cp16(sB + r * ROWB + cc * 16,
                 (const char*)(g_Ka + (brow0 + r) * KD + c0) + cc * 16);
        }
        asm volatile("cp.async.commit_group;" ::: "memory");
    };

    float acc[4][4][4];
    #pragma unroll
    for (int i = 0; i < 4; ++i)
        #pragma unroll
        for (int j = 0; j < 4; ++j)
            #pragma unroll
            for (int v = 0; v < 4; ++v) acc[i][j][v] = 0.f;

    issueChunk(0);
    if (myChunks > 1) issueChunk(1);

    const uint32_t aB = smb + (uint32_t)(wm * 64 + (lane & 15)) * ROWB + (lane >> 4) * 16;
    const uint32_t bB = smb + B_OFF + (uint32_t)(wn * 32 + (lane & 15)) * ROWB + (lane >> 4) * 16;

    uint32_t afr[2][4][4];    // double-buffered A fragments
    uint32_t bfr[2][4][2];    // double-buffered B fragments

    auto ldFrag = [&](int buf, uint32_t so, int kc) {
        #pragma unroll
        for (int mt = 0; mt < 4; ++mt)
            ldsm4(afr[buf][mt][0], afr[buf][mt][1], afr[buf][mt][2], afr[buf][mt][3],
                  aB + so + kc * 32 + mt * (16 * ROWB));
        #pragma unroll
        for (int nb = 0; nb < 2; ++nb) {
            uint32_t r0, r1, r2, r3;
            ldsm4(r0, r1, r2, r3, bB + so + kc * 32 + nb * (16 * ROWB));
            bfr[buf][2 * nb][0] = r0;     bfr[buf][2 * nb][1] = r2;
            bfr[buf][2 * nb + 1][0] = r1; bfr[buf][2 * nb + 1][1] = r3;
        }
    };

    #pragma unroll 1
    for (int c = 0; c < myChunks; ++c) {
        const int t = c / 3, s = c - t * 3;

        if (c + 1 < myChunks) asm volatile("cp.async.wait_group 1;" ::: "memory");
        else                  asm volatile("cp.async.wait_group 0;" ::: "memory");
        __syncthreads();                     // data of chunk c visible; slot of c-1 free
        if (c + 2 < myChunks) issueChunk(c + 2);

        const uint32_t so = s * STAGE;
        ldFrag(0, so, 0);
        #pragma unroll
        for (int kc = 0; kc < 4; ++kc) {
            const int cur = kc & 1;
            if (kc < 3) ldFrag(cur ^ 1, so, kc + 1);   // prefetch before consuming cur
            #pragma unroll
            for (int mt = 0; mt < 4; ++mt)
                #pragma unroll
                for (int nt = 0; nt < 4; ++nt)
                    mma16816(acc[mt][nt], afr[cur][mt], bfr[cur][nt]);
        }

        if (s == 2) {
            // epilogue for this tile; overlaps in-flight loads of next tile
            const int tileIdx = bid + t * grid;
            const int h = tileIdx >> 7, rem = tileIdx & 127;
            float* Cb = C + ((size_t)h * NN + (size_t)(rem >> 3) * 128 + wm * 64) * TT
                          + (size_t)(rem & 7) * 256 + wn * 32;
            const int r = lane >> 2, cc = (lane & 3) * 2;
            #pragma unroll
            for (int mt = 0; mt < 4; ++mt) {
                #pragma unroll
                for (int nt = 0; nt < 4; ++nt) {
                    float2 v0 = make_float2(acc[mt][nt][0], acc[mt][nt][1]);
                    float2 v1 = make_float2(acc[mt][nt][2], acc[mt][nt][3]);
                    __stcs((float2*)(Cb + (size_t)(mt * 16 + r) * TT + nt * 8 + cc), v0);
                    __stcs((float2*)(Cb + (size_t)(mt * 16 + r + 8) * TT + nt * 8 + cc), v1);
                    acc[mt][nt][0] = 0.f; acc[mt][nt][1] = 0.f;
                    acc[mt][nt][2] = 0.f; acc[mt][nt][3] = 0.f;
                }
            }
        }
    }
}

// ---------------------------------------------------------------------------
extern "C" void kernel_launch(void* const* d_in, const int* in_sizes, int n_in,
                              void* d_out, int out_size) {
    const float* q       = (const float*)d_in[0];
    const float* k_orig  = (const float*)d_in[1];
    const float* k_quant = (const float*)d_in[2];
    const float* G       = (const float*)d_in[3];
    float* out = (float*)d_out;

    int dev = 0, nsm = 148;
    cudaGetDevice(&dev);
    cudaDeviceGetAttribute(&nsm, cudaDevAttrMultiProcessorCount, dev);

    cudaFuncSetAttribute(gemm_persist, cudaFuncAttributeMaxDynamicSharedMemorySize, SMEM_TOTAL);

    prep_all<<<4096, 256>>>(q, k_orig, k_quant, G);
    gemm_persist<<<nsm, 512, SMEM_TOTAL>>>(out);
}